// round 13
// baseline (speedup 1.0000x reference)
#include <cuda_runtime.h>
#include <math.h>

#define NB     8
#define NPTS   8192
#define NQ     2048
#define KNN_K  16
#define NSAMP  (NB*NQ*KNN_K)        /* 262144 */
#define OXYZ   (NB*3*NQ)            /* 49152  */

#define CLU    8                    /* cluster size for FPS */
#define FPS_T  128                  /* threads per FPS CTA  */
#define NWARP  (FPS_T/32)           /* 4 warps              */
#define NREC   (CLU*NWARP)          /* 32 records per iter  */
#define SLICE  (NPTS/CLU)           /* 1024 points per CTA  */

// ---------------- static scratch (no allocations) ----------------
__device__ int    g_fps[NB*NQ];
__device__ int    g_knn[NSAMP];
__device__ float4 g_xyz4[NB*NPTS];                 // {x,y,z,|p|^2}
__device__ float4 g_qxyz[NB*NQ];                   // selected query points
__device__ float  g_ptsT[(size_t)NB*NPTS*64];      // points transposed (B,N,64)
__device__ float  g_Y1[(size_t)NSAMP*64];
__device__ float  g_Y2[(size_t)NSAMP*64];
__device__ double g_sum1[64], g_sq1[64], g_sum2[64], g_sq2[64];
__device__ float  g_s1[64], g_t1[64], g_s2[64], g_t2[64];

typedef unsigned long long ull;

// -------- packed f32x2 helpers --------
__device__ __forceinline__ ull pk2(float a, float b) {
    ull r; asm("mov.b64 %0, {%1, %2};" : "=l"(r) : "f"(a), "f"(b)); return r;
}
__device__ __forceinline__ void upk2(float& a, float& b, ull r) {
    asm("mov.b64 {%0, %1}, %2;" : "=f"(a), "=f"(b) : "l"(r));
}
__device__ __forceinline__ ull add2(ull a, ull b) {
    ull r; asm("add.rn.f32x2 %0, %1, %2;" : "=l"(r) : "l"(a), "l"(b)); return r;
}
__device__ __forceinline__ ull mul2(ull a, ull b) {
    ull r; asm("mul.rn.f32x2 %0, %1, %2;" : "=l"(r) : "l"(a), "l"(b)); return r;
}
__device__ __forceinline__ ull fma2(ull a, ull b, ull c) {
    ull r; asm("fma.rn.f32x2 %0, %1, %2, %3;" : "=l"(r) : "l"(a), "l"(b), "l"(c)); return r;
}
__device__ __forceinline__ float sq3(float a, float b, float c) {
    return __fadd_rn(__fadd_rn(__fmul_rn(a,a), __fmul_rn(b,b)), __fmul_rn(c,c));
}

// -------- cluster / mbarrier helpers --------
__device__ __forceinline__ unsigned smem_u32(const void* p) {
    return (unsigned)__cvta_generic_to_shared(p);
}
__device__ __forceinline__ unsigned my_ctarank() {
    unsigned r; asm("mov.u32 %0, %%cluster_ctarank;" : "=r"(r)); return r;
}
__device__ __forceinline__ unsigned mapa_u32(unsigned addr, unsigned rank) {
    unsigned r; asm("mapa.shared::cluster.u32 %0, %1, %2;" : "=r"(r) : "r"(addr), "r"(rank));
    return r;
}
__device__ __forceinline__ void mbar_init(unsigned addr, unsigned cnt) {
    asm volatile("mbarrier.init.shared.b64 [%0], %1;" :: "r"(addr), "r"(cnt) : "memory");
}
__device__ __forceinline__ void st_async_u64(unsigned raddr, ull v, unsigned rmbar) {
    asm volatile("st.async.weak.shared::cluster.mbarrier::complete_tx::bytes.b64 [%0], %1, [%2];"
                 :: "r"(raddr), "l"(v), "r"(rmbar) : "memory");
}
__device__ __forceinline__ void mbar_expect_tx(unsigned addr, unsigned bytes) {
    asm volatile("mbarrier.arrive.expect_tx.shared::cta.b64 _, [%0], %1;"
                 :: "r"(addr), "r"(bytes) : "memory");
}
__device__ __forceinline__ void mbar_wait(unsigned addr, unsigned par) {
    unsigned done;
    do {
        asm volatile("{\n\t.reg .pred p;\n\t"
            "mbarrier.try_wait.parity.acquire.cluster.shared::cta.b64 p, [%1], %2, 0x989680;\n\t"
            "selp.b32 %0, 1, 0, p;\n\t}"
            : "=r"(done) : "r"(addr), "r"(par) : "memory");
    } while (!done);
}
#define CLUSTER_SYNC_() do { \
    asm volatile("barrier.cluster.arrive.aligned;" ::: "memory"); \
    asm volatile("barrier.cluster.wait.aligned;"   ::: "memory"); } while (0)

// =====================================================================
// K0: FPS over 8-CTA clusters, one cluster per batch. Per-WARP direct
// publish: each warp's lanes 0..7 push its winner record to all CTAs
// (no __syncthreads / CTA-level reduce on critical path). Each CTA
// waits for 32 records (768B tx), takes the 32-slot max.
// =====================================================================
extern "C" __global__ void __launch_bounds__(FPS_T, 1) __cluster_dims__(CLU, 1, 1)
k_fps(const float* __restrict__ xyz)
{
    __shared__ float4 sp4[SLICE];            // 16 KB slice {x,y,z,0}
    __shared__ ull    rkey[2][NREC];         // [buf][src*4+wid] keys
    __shared__ ull    rxy [2][NREC];         // packed {x,y}
    __shared__ ull    rz  [2][NREC];         // packed {z,0}
    __shared__ ull    mb[2];                 // alternating tx mbarriers

    const int tid  = threadIdx.x;
    const int lane = tid & 31, wid = tid >> 5;
    const unsigned rank = my_ctarank();
    const int b = blockIdx.x / CLU;
    const float* X = xyz + b*3*NPTS;

    for (int i = tid; i < SLICE; i += FPS_T) {
        int gi = (int)rank*SLICE + i;
        sp4[i] = make_float4(X[gi], X[NPTS+gi], X[2*NPTS+gi], 0.f);
    }
    if (tid == 0) {
        mbar_init(smem_u32(&mb[0]), 1);
        mbar_init(smem_u32(&mb[1]), 1);
        if (rank == 0) g_fps[b*NQ] = 0;
    }
    __syncthreads();
    CLUSTER_SYNC_();

    // 8 points/thread -> 4 packed f32x2 pairs; local idx = tid + m*FPS_T
    ull px2[4], py2[4], pz2[4]; float dd[8];
    #pragma unroll
    for (int j = 0; j < 4; j++) {
        float4 a = sp4[tid + (2*j)*FPS_T];
        float4 c = sp4[tid + (2*j+1)*FPS_T];
        px2[j] = pk2(a.x, c.x); py2[j] = pk2(a.y, c.y); pz2[j] = pk2(a.z, c.z);
        dd[2*j] = 1e10f; dd[2*j+1] = 1e10f;
    }
    float Px = X[0], Py = X[NPTS], Pz = X[2*NPTS];

    // hoisted remote addresses: lane (<8) = target rank; slot = rank*4+wid
    unsigned rko[2], rxo[2], rzo[2], rmb[2];
    if (lane < CLU) {
        const int slot = (int)rank*NWARP + wid;
        #pragma unroll
        for (int q = 0; q < 2; q++) {
            rko[q] = mapa_u32(smem_u32(&rkey[q][slot]), (unsigned)lane);
            rxo[q] = mapa_u32(smem_u32(&rxy [q][slot]), (unsigned)lane);
            rzo[q] = mapa_u32(smem_u32(&rz  [q][slot]), (unsigned)lane);
            rmb[q] = mapa_u32(smem_u32(&mb[q]),          (unsigned)lane);
        }
    }
    const unsigned mbA = smem_u32(&mb[0]), mbB = smem_u32(&mb[1]);
    int parA = 0, parB = 0;

    for (int it = 1; it < NQ; ++it) {
        const int ib = (it - 1) & 1;
        if (tid == 0) mbar_expect_tx(ib ? mbB : mbA, 24u * NREC);
        // ---- local distance update + per-thread best (exact non-fused) ----
        ull nPx = pk2(-Px,-Px), nPy = pk2(-Py,-Py), nPz = pk2(-Pz,-Pz);
        float bv = -1.f; int bm = 0;
        #pragma unroll
        for (int j = 0; j < 4; j++) {
            ull dx = add2(px2[j], nPx);
            ull dy = add2(py2[j], nPy);
            ull dz = add2(pz2[j], nPz);
            ull s  = add2(add2(mul2(dx,dx), mul2(dy,dy)), mul2(dz,dz));
            float lo, hi; upk2(lo, hi, s);
            float n0 = fminf(dd[2*j],   lo); dd[2*j]   = n0;
            float n1 = fminf(dd[2*j+1], hi); dd[2*j+1] = n1;
            if (n0 > bv) { bv = n0; bm = 2*j; }
            if (n1 > bv) { bv = n1; bm = 2*j+1; }
        }
        int gidx = (int)rank*SLICE + tid + bm*FPS_T;
        // ---- warp argmax, branchless min-index tie-break ----
        unsigned vb  = __float_as_uint(bv);
        unsigned mx  = __reduce_max_sync(0xffffffffu, vb);
        unsigned cnd = (vb == mx) ? (unsigned)gidx : 0x7fffffffu;
        unsigned wix = __reduce_min_sync(0xffffffffu, cnd);
        // ---- per-warp direct publish to all 8 CTAs ----
        if (lane < CLU) {
            ull k = ((ull)mx << 32) | (ull)(0xFFFFFFFFu - wix);
            float4 w = sp4[(int)wix - (int)rank*SLICE];   // warp-uniform broadcast
            st_async_u64(rko[ib], k,             rmb[ib]);
            st_async_u64(rxo[ib], pk2(w.x, w.y), rmb[ib]);
            st_async_u64(rzo[ib], pk2(w.z, 0.f), rmb[ib]);
        }
        // ---- wait 32 records (768B tx), global 32-slot argmax ----
        if (ib == 0) { mbar_wait(mbA, (unsigned)parA); parA ^= 1; }
        else         { mbar_wait(mbB, (unsigned)parB); parB ^= 1; }
        {
            const ulonglong2* rv = (const ulonglong2*)rkey[ib];
            ull k = 0; int s = 0;
            #pragma unroll
            for (int i = 0; i < NREC/2; i++) {
                ulonglong2 p2 = rv[i];
                if (p2.x > k) { k = p2.x; s = 2*i; }
                if (p2.y > k) { k = p2.y; s = 2*i+1; }
            }
            float zx; upk2(Px, Py, rxy[ib][s]);
            upk2(Pz, zx, rz[ib][s]);
            if (rank == 0 && tid == 0)
                g_fps[b*NQ + it] = (int)(0xFFFFFFFFu - (unsigned)k);
        }
    }
    CLUSTER_SYNC_();
}

// =====================================================================
// K1: aux — xyz4 build (+ stat zero) and points transpose
// =====================================================================
extern "C" __global__ void __launch_bounds__(1024)
k_aux(const float* __restrict__ xyz, const float* __restrict__ pts)
{
    extern __shared__ float sm[];
    const int tid = threadIdx.x;
    const int bid = blockIdx.x;
    if (bid < 64) {
        int b = bid >> 3;
        int i = ((bid & 7) << 10) + tid;
        const float* X = xyz + b*3*NPTS;
        float x = X[i], y = X[NPTS+i], z = X[2*NPTS+i];
        g_xyz4[b*NPTS + i] = make_float4(x, y, z, sq3(x,y,z));
        if (bid == 0 && tid < 64) {
            g_sum1[tid]=0.0; g_sq1[tid]=0.0; g_sum2[tid]=0.0; g_sq2[tid]=0.0;
        }
    } else {
        int id = bid - 64;
        int b  = id >> 5;
        int nb = (id & 31) << 8;
        float* tile = sm;                          // [256][68]
        const float* Pp = pts + (size_t)b*64*NPTS;
        for (int i = tid; i < 64*256; i += 1024) {
            int c = i >> 8, n = i & 255;
            tile[n*68 + c] = Pp[c*NPTS + nb + n];
        }
        __syncthreads();
        for (int i = tid; i < 256*16; i += 1024) {
            int n = i >> 4, c4 = (i & 15) << 2;
            float4 v = *(const float4*)&tile[n*68 + c4];
            *(float4*)&g_ptsT[((size_t)(b*NPTS + nb + n))*64 + c4] = v;
        }
    }
}

// =====================================================================
// K2: KNN 16-NN, split-scan + lexicographic merge (unchanged from R10)
// =====================================================================
extern "C" __global__ void __launch_bounds__(256)
k_knn(float* __restrict__ out)
{
    extern __shared__ float smraw[];
    float4* sp = (float4*)smraw;                 // [8192] = 128 KB
    float*  md = (float*)(sp + NPTS);            // [16][256]
    int*    mi = (int*)(md + 16*256);            // [16][256]
    const int tid  = threadIdx.x;
    const int qi   = tid & 127;
    const int half = tid >> 7;
    const int b = blockIdx.x >> 4;
    const int q = ((blockIdx.x & 15) << 7) + qi;

    for (int i = tid; i < NPTS; i += 256)
        sp[i] = g_xyz4[b*NPTS + i];
    __syncthreads();

    const int i0 = g_fps[b*NQ + q];
    float4 qv = sp[i0];
    if (half == 0) {
        g_qxyz[b*NQ + q] = qv;
        out[b*3*NQ + q]        = qv.x;
        out[b*3*NQ + NQ + q]   = qv.y;
        out[b*3*NQ + 2*NQ + q] = qv.z;
    }

    float nd[16]; int ni[16];
    #pragma unroll
    for (int j = 0; j < 16; j++) { nd[j] = 3.0e38f; ni[j] = 0; }
    const int beg = half << 12, fin = beg + 4096;
    #pragma unroll 4
    for (int i = beg; i < fin; i++) {
        float4 p = sp[i];
        float dot = __fadd_rn(__fadd_rn(__fmul_rn(p.x,qv.x), __fmul_rn(p.y,qv.y)),
                              __fmul_rn(p.z,qv.z));
        float d = __fsub_rn(__fadd_rn(qv.w, p.w), __fmul_rn(2.0f, dot));
        if (d < nd[15]) {
            nd[15] = d; ni[15] = i;
            #pragma unroll
            for (int j = 15; j > 0; --j) {
                if (nd[j] < nd[j-1]) {
                    float td = nd[j]; nd[j] = nd[j-1]; nd[j-1] = td;
                    int   ti = ni[j]; ni[j] = ni[j-1]; ni[j-1] = ti;
                }
            }
        }
    }
    #pragma unroll
    for (int j = 0; j < 16; j++) { md[j*256 + tid] = nd[j]; mi[j*256 + tid] = ni[j]; }
    __syncthreads();
    if (half == 0) {
        const int base = (b*NQ + q)*KNN_K;
        int ia = 0, ic = 0;
        #pragma unroll
        for (int j = 0; j < 16; j++) {
            float da = (ia < 16) ? md[ia*256 + qi]       : 3.4e38f;
            float dc = (ic < 16) ? md[ic*256 + 128 + qi] : 3.4e38f;
            if (da <= dc) { g_knn[base + j] = mi[ia*256 + qi];       ia++; }
            else          { g_knn[base + j] = mi[ic*256 + 128 + qi]; ic++; }
        }
    }
}

// =====================================================================
// K3: layer1 GEMM (64 x 67), 128-sample tiles -> 4 CTAs/SM, + BN1 stats
// =====================================================================
extern "C" __global__ void __launch_bounds__(256, 4)
k_l1(const float* __restrict__ W1, const float* __restrict__ b1)
{
    extern __shared__ float sm[];
    float* sW  = sm;            // 67*64  = 4288
    float* sF  = sW + 4288;     // 67*128 = 8576
    float* shS = sF + 8576;     // 64
    float* shQ = shS + 64;      // 64  -> total 12992 fl = 51968 B
    const int tid = threadIdx.x, blk = blockIdx.x;

    for (int i = tid; i < 4288; i += 256)
        sW[i] = W1[(i & 63)*67 + (i >> 6)];
    if (tid < 64) { shS[tid] = 0.f; shQ[tid] = 0.f; }
    {   // gather: 2 threads per sample (halves of 64 pt-channels)
        int s = tid >> 1, h = tid & 1;
        int S = blk*128 + s;
        int b = S >> 15; int q = (S & 32767) >> 4;
        int n = g_knn[S];
        float4 qv = g_qxyz[b*NQ + q];
        if (h == 0) {
            float4 pv = g_xyz4[b*NPTS + n];
            sF[s]       = pv.x - qv.x;
            sF[128 + s] = pv.y - qv.y;
            sF[256 + s] = pv.z - qv.z;
        }
        const float4* pr = (const float4*)&g_ptsT[(size_t)(b*NPTS + n)*64];
        #pragma unroll
        for (int j = 0; j < 8; j++) {
            float4 v = pr[h*8 + j];
            int c = 3 + h*32 + (j << 2);
            sF[(c+0)*128+s]=v.x; sF[(c+1)*128+s]=v.y;
            sF[(c+2)*128+s]=v.z; sF[(c+3)*128+s]=v.w;
        }
    }
    __syncthreads();

    const int tc = tid & 7, tr = tid >> 3;   // 8ch x 4samples per thread
    ull acc2[8][2];
    #pragma unroll
    for (int ci = 0; ci < 8; ci++) {
        float bb = __ldg(&b1[(tc<<3)+ci]);
        acc2[ci][0] = pk2(bb, bb); acc2[ci][1] = acc2[ci][0];
    }
    #pragma unroll 1
    for (int k = 0; k < 67; k++) {
        float4 wa = *(float4*)&sW[k*64 + (tc<<3)];
        float4 wb = *(float4*)&sW[k*64 + (tc<<3) + 4];
        float4 fa = *(float4*)&sF[k*128 + (tr<<2)];
        ull f2[2] = {pk2(fa.x,fa.y), pk2(fa.z,fa.w)};
        float w[8] = {wa.x,wa.y,wa.z,wa.w,wb.x,wb.y,wb.z,wb.w};
        #pragma unroll
        for (int ci = 0; ci < 8; ci++) {
            ull wp = pk2(w[ci], w[ci]);
            acc2[ci][0] = fma2(wp, f2[0], acc2[ci][0]);
            acc2[ci][1] = fma2(wp, f2[1], acc2[ci][1]);
        }
    }
    float acc[8][4];
    #pragma unroll
    for (int ci = 0; ci < 8; ci++) {
        upk2(acc[ci][0], acc[ci][1], acc2[ci][0]);
        upk2(acc[ci][2], acc[ci][3], acc2[ci][1]);
    }
    #pragma unroll
    for (int ci = 0; ci < 8; ci++) {
        float s = 0.f, qq = 0.f;
        #pragma unroll
        for (int si = 0; si < 4; si++) { float v = acc[ci][si]; s += v; qq = fmaf(v,v,qq); }
        atomicAdd(&shS[(tc<<3)+ci], s);
        atomicAdd(&shQ[(tc<<3)+ci], qq);
    }
    #pragma unroll
    for (int si = 0; si < 4; si++) {
        size_t So = (size_t)(blk*128 + (tr<<2) + si);
        *(float4*)&g_Y1[So*64 + (tc<<3)]     = make_float4(acc[0][si],acc[1][si],acc[2][si],acc[3][si]);
        *(float4*)&g_Y1[So*64 + (tc<<3) + 4] = make_float4(acc[4][si],acc[5][si],acc[6][si],acc[7][si]);
    }
    __syncthreads();
    if (tid < 64) {
        atomicAdd(&g_sum1[tid], (double)shS[tid]);
        atomicAdd(&g_sq1[tid],  (double)shQ[tid]);
    }
}

// =====================================================================
// BN finalize
// =====================================================================
extern "C" __global__ void k_fin(const float* __restrict__ g,
                                 const float* __restrict__ be, int layer)
{
    int c = threadIdx.x;
    double su = layer ? g_sum2[c] : g_sum1[c];
    double sq = layer ? g_sq2[c]  : g_sq1[c];
    double mean = su * (1.0/262144.0);
    double var  = sq * (1.0/262144.0) - mean*mean;
    double inv  = 1.0 / sqrt(var + 1e-5);
    float sc = (float)((double)g[c] * inv);
    float sh = (float)((double)be[c] - mean * (double)g[c] * inv);
    if (layer) { g_s2[c]=sc; g_t2[c]=sh; } else { g_s1[c]=sc; g_t1[c]=sh; }
}

// =====================================================================
// K5: layer2 GEMM (64 x 64), 128-sample tiles, BN1 fused, + BN2 stats
// =====================================================================
extern "C" __global__ void __launch_bounds__(256, 4)
k_l2(const float* __restrict__ W2, const float* __restrict__ b2)
{
    extern __shared__ float sm[];
    float* sW  = sm;            // 4096
    float* sH  = sW + 4096;     // 64*128 = 8192
    float* ss  = sH + 8192;     // 64
    float* st  = ss + 64;       // 64
    float* shS = st + 64;       // 64
    float* shQ = shS + 64;      // 64 -> 12544 fl = 50176 B
    const int tid = threadIdx.x, blk = blockIdx.x;

    for (int i = tid; i < 4096; i += 256)
        sW[i] = W2[(i & 63)*64 + (i >> 6)];
    if (tid < 64) { ss[tid]=g_s1[tid]; st[tid]=g_t1[tid]; shS[tid]=0.f; shQ[tid]=0.f; }
    __syncthreads();
    {
        int s = tid >> 1, h = tid & 1;
        int S = blk*128 + s;
        const float4* yr = (const float4*)&g_Y1[(size_t)S*64 + h*32];
        #pragma unroll
        for (int j = 0; j < 8; j++) {
            float4 y = yr[j];
            int c = h*32 + (j << 2);
            float4 sv = *(float4*)&ss[c];
            float4 tv = *(float4*)&st[c];
            sH[(c+0)*128+s] = fmaxf(fmaf(y.x,sv.x,tv.x),0.f);
            sH[(c+1)*128+s] = fmaxf(fmaf(y.y,sv.y,tv.y),0.f);
            sH[(c+2)*128+s] = fmaxf(fmaf(y.z,sv.z,tv.z),0.f);
            sH[(c+3)*128+s] = fmaxf(fmaf(y.w,sv.w,tv.w),0.f);
        }
    }
    __syncthreads();

    const int tc = tid & 7, tr = tid >> 3;
    ull acc2[8][2];
    #pragma unroll
    for (int ci = 0; ci < 8; ci++) {
        float bb = __ldg(&b2[(tc<<3)+ci]);
        acc2[ci][0] = pk2(bb, bb); acc2[ci][1] = acc2[ci][0];
    }
    #pragma unroll 1
    for (int k = 0; k < 64; k++) {
        float4 wa = *(float4*)&sW[k*64 + (tc<<3)];
        float4 wb = *(float4*)&sW[k*64 + (tc<<3) + 4];
        float4 fa = *(float4*)&sH[k*128 + (tr<<2)];
        ull f2[2] = {pk2(fa.x,fa.y), pk2(fa.z,fa.w)};
        float w[8] = {wa.x,wa.y,wa.z,wa.w,wb.x,wb.y,wb.z,wb.w};
        #pragma unroll
        for (int ci = 0; ci < 8; ci++) {
            ull wp = pk2(w[ci], w[ci]);
            acc2[ci][0] = fma2(wp, f2[0], acc2[ci][0]);
            acc2[ci][1] = fma2(wp, f2[1], acc2[ci][1]);
        }
    }
    float acc[8][4];
    #pragma unroll
    for (int ci = 0; ci < 8; ci++) {
        upk2(acc[ci][0], acc[ci][1], acc2[ci][0]);
        upk2(acc[ci][2], acc[ci][3], acc2[ci][1]);
    }
    #pragma unroll
    for (int ci = 0; ci < 8; ci++) {
        float s = 0.f, qq = 0.f;
        #pragma unroll
        for (int si = 0; si < 4; si++) { float v = acc[ci][si]; s += v; qq = fmaf(v,v,qq); }
        atomicAdd(&shS[(tc<<3)+ci], s);
        atomicAdd(&shQ[(tc<<3)+ci], qq);
    }
    #pragma unroll
    for (int si = 0; si < 4; si++) {
        size_t So = (size_t)(blk*128 + (tr<<2) + si);
        *(float4*)&g_Y2[So*64 + (tc<<3)]     = make_float4(acc[0][si],acc[1][si],acc[2][si],acc[3][si]);
        *(float4*)&g_Y2[So*64 + (tc<<3) + 4] = make_float4(acc[4][si],acc[5][si],acc[6][si],acc[7][si]);
    }
    __syncthreads();
    if (tid < 64) {
        atomicAdd(&g_sum2[tid], (double)shS[tid]);
        atomicAdd(&g_sq2[tid],  (double)shQ[tid]);
    }
}

// =====================================================================
// K7: layer3 GEMM (128 x 64), 128-sample tiles (8 queries/block),
//     BN2 fused on load, fused max-pool, writes new_feat.
// =====================================================================
extern "C" __global__ void __launch_bounds__(256, 3)
k_l3(const float* __restrict__ W3, const float* __restrict__ b3,
     float* __restrict__ out)
{
    extern __shared__ float sm[];
    float* sW = sm;             // 64*128 = 8192 (layout [k][o])
    float* sH = sW + 8192;      // 64*128 = 8192
    float* ss = sH + 8192;      // 64
    float* st = ss + 64;        // 64 -> 16512 fl = 66048 B
    const int tid = threadIdx.x, blk = blockIdx.x;

    for (int i = tid; i < 8192; i += 256)
        sW[i] = W3[(i & 127)*64 + (i >> 7)];
    if (tid < 64) { ss[tid]=g_s2[tid]; st[tid]=g_t2[tid]; }
    __syncthreads();
    {
        int s = tid >> 1, h = tid & 1;
        int S = blk*128 + s;
        const float4* yr = (const float4*)&g_Y2[(size_t)S*64 + h*32];
        #pragma unroll
        for (int j = 0; j < 8; j++) {
            float4 y = yr[j];
            int c = h*32 + (j << 2);
            float4 sv = *(float4*)&ss[c];
            float4 tv = *(float4*)&st[c];
            sH[(c+0)*128+s] = fmaxf(fmaf(y.x,sv.x,tv.x),0.f);
            sH[(c+1)*128+s] = fmaxf(fmaf(y.y,sv.y,tv.y),0.f);
            sH[(c+2)*128+s] = fmaxf(fmaf(y.z,sv.z,tv.z),0.f);
            sH[(c+3)*128+s] = fmaxf(fmaf(y.w,sv.w,tv.w),0.f);
        }
    }
    __syncthreads();

    const int tc = tid & 7, tr = tid >> 3;    // 4 samples per thread
    const int w  = tid >> 5;                  // warp = query (8 q/block)
    const int qg = blk*8 + w;
    const int b = qg >> 11, qq = qg & 2047;
    float* feat = out + OXYZ + (size_t)b*128*NQ;

    for (int h = 0; h < 2; h++) {             // two 64-channel halves
        ull acc2[8][2];
        #pragma unroll
        for (int ci = 0; ci < 8; ci++) {
            float bb = __ldg(&b3[h*64 + (tc<<3)+ci]);
            acc2[ci][0] = pk2(bb, bb); acc2[ci][1] = acc2[ci][0];
        }
        #pragma unroll 1
        for (int k = 0; k < 64; k++) {
            float4 wa = *(float4*)&sW[k*128 + h*64 + (tc<<3)];
            float4 wb = *(float4*)&sW[k*128 + h*64 + (tc<<3) + 4];
            float4 fa = *(float4*)&sH[k*128 + (tr<<2)];
            ull f2[2] = {pk2(fa.x,fa.y), pk2(fa.z,fa.w)};
            float w8[8] = {wa.x,wa.y,wa.z,wa.w,wb.x,wb.y,wb.z,wb.w};
            #pragma unroll
            for (int ci = 0; ci < 8; ci++) {
                ull wp = pk2(w8[ci], w8[ci]);
                acc2[ci][0] = fma2(wp, f2[0], acc2[ci][0]);
                acc2[ci][1] = fma2(wp, f2[1], acc2[ci][1]);
            }
        }
        // max over 4 samples, then lanes {l, l^8, l^16, l^24} = full query
        #pragma unroll
        for (int ci = 0; ci < 8; ci++) {
            float a0, a1, b0, b1;
            upk2(a0, a1, acc2[ci][0]);
            upk2(b0, b1, acc2[ci][1]);
            float m = fmaxf(fmaxf(a0, a1), fmaxf(b0, b1));
            m = fmaxf(m, __shfl_xor_sync(0xffffffffu, m, 8));
            m = fmaxf(m, __shfl_xor_sync(0xffffffffu, m, 16));
            if ((tid & 31) < 8)
                feat[(h*64 + (tc<<3) + ci)*NQ + qq] = m;
        }
    }
}

// =====================================================================
extern "C" void kernel_launch(void* const* d_in, const int* in_sizes, int n_in,
                              void* d_out, int out_size)
{
    const float* xyz = (const float*)d_in[0];
    const float* pts = (const float*)d_in[1];
    const float* W1  = (const float*)d_in[2];
    const float* b1  = (const float*)d_in[3];
    const float* g1  = (const float*)d_in[4];
    const float* be1 = (const float*)d_in[5];
    const float* W2  = (const float*)d_in[6];
    const float* b2  = (const float*)d_in[7];
    const float* g2  = (const float*)d_in[8];
    const float* be2 = (const float*)d_in[9];
    const float* W3  = (const float*)d_in[10];
    const float* b3  = (const float*)d_in[11];
    float* out = (float*)d_out;

    cudaFuncSetAttribute(k_aux, cudaFuncAttributeMaxDynamicSharedMemorySize, 69632);
    cudaFuncSetAttribute(k_knn, cudaFuncAttributeMaxDynamicSharedMemorySize, 163840);
    cudaFuncSetAttribute(k_l1,  cudaFuncAttributeMaxDynamicSharedMemorySize, 51968);
    cudaFuncSetAttribute(k_l2,  cudaFuncAttributeMaxDynamicSharedMemorySize, 50176);
    cudaFuncSetAttribute(k_l3,  cudaFuncAttributeMaxDynamicSharedMemorySize, 66048);

    k_fps<<<NB*CLU, FPS_T>>>(xyz);
    k_aux<<<320, 1024, 69632>>>(xyz, pts);
    k_knn<<<128, 256, 163840>>>(out);
    k_l1 <<<2048, 256, 51968>>>(W1, b1);
    k_fin<<<1, 64>>>(g1, be1, 0);
    k_l2 <<<2048, 256, 50176>>>(W2, b2);
    k_fin<<<1, 64>>>(g2, be2, 1);
    k_l3 <<<2048, 256, 66048>>>(W3, b3, out);
}

// round 14
// speedup vs baseline: 1.3073x; 1.3073x over previous
#include <cuda_runtime.h>
#include <math.h>

#define NB     8
#define NPTS   8192
#define NQ     2048
#define KNN_K  16
#define NSAMP  (NB*NQ*KNN_K)        /* 262144 */
#define OXYZ   (NB*3*NQ)            /* 49152  */

#define CLU    8                    /* cluster size for FPS */
#define FPS_T  32                   /* ONE warp per FPS CTA */
#define SLICE  (NPTS/CLU)           /* 1024 points per CTA  */
#define PPT    (SLICE/FPS_T)        /* 32 points per thread */

// ---------------- static scratch (no allocations) ----------------
__device__ int    g_fps[NB*NQ];
__device__ int    g_knn[NSAMP];
__device__ float4 g_xyz4[NB*NPTS];                 // {x,y,z,|p|^2}
__device__ float4 g_qxyz[NB*NQ];                   // selected query points
__device__ float  g_ptsT[(size_t)NB*NPTS*64];      // points transposed (B,N,64)
__device__ float  g_Y1[(size_t)NSAMP*64];
__device__ float  g_Y2[(size_t)NSAMP*64];
__device__ double g_sum1[64], g_sq1[64], g_sum2[64], g_sq2[64];
__device__ float  g_s1[64], g_t1[64], g_s2[64], g_t2[64];

typedef unsigned long long ull;

// -------- packed f32x2 helpers --------
__device__ __forceinline__ ull pk2(float a, float b) {
    ull r; asm("mov.b64 %0, {%1, %2};" : "=l"(r) : "f"(a), "f"(b)); return r;
}
__device__ __forceinline__ void upk2(float& a, float& b, ull r) {
    asm("mov.b64 {%0, %1}, %2;" : "=f"(a), "=f"(b) : "l"(r));
}
__device__ __forceinline__ ull add2(ull a, ull b) {
    ull r; asm("add.rn.f32x2 %0, %1, %2;" : "=l"(r) : "l"(a), "l"(b)); return r;
}
__device__ __forceinline__ ull mul2(ull a, ull b) {
    ull r; asm("mul.rn.f32x2 %0, %1, %2;" : "=l"(r) : "l"(a), "l"(b)); return r;
}
__device__ __forceinline__ ull fma2(ull a, ull b, ull c) {
    ull r; asm("fma.rn.f32x2 %0, %1, %2, %3;" : "=l"(r) : "l"(a), "l"(b), "l"(c)); return r;
}
__device__ __forceinline__ float sq3(float a, float b, float c) {
    return __fadd_rn(__fadd_rn(__fmul_rn(a,a), __fmul_rn(b,b)), __fmul_rn(c,c));
}

// -------- cluster / mbarrier helpers --------
__device__ __forceinline__ unsigned smem_u32(const void* p) {
    return (unsigned)__cvta_generic_to_shared(p);
}
__device__ __forceinline__ unsigned my_ctarank() {
    unsigned r; asm("mov.u32 %0, %%cluster_ctarank;" : "=r"(r)); return r;
}
__device__ __forceinline__ unsigned mapa_u32(unsigned addr, unsigned rank) {
    unsigned r; asm("mapa.shared::cluster.u32 %0, %1, %2;" : "=r"(r) : "r"(addr), "r"(rank));
    return r;
}
__device__ __forceinline__ void mbar_init(unsigned addr, unsigned cnt) {
    asm volatile("mbarrier.init.shared.b64 [%0], %1;" :: "r"(addr), "r"(cnt) : "memory");
}
__device__ __forceinline__ void st_async_u64(unsigned raddr, ull v, unsigned rmbar) {
    asm volatile("st.async.weak.shared::cluster.mbarrier::complete_tx::bytes.b64 [%0], %1, [%2];"
                 :: "r"(raddr), "l"(v), "r"(rmbar) : "memory");
}
__device__ __forceinline__ void mbar_expect_tx(unsigned addr, unsigned bytes) {
    asm volatile("mbarrier.arrive.expect_tx.shared::cta.b64 _, [%0], %1;"
                 :: "r"(addr), "r"(bytes) : "memory");
}
__device__ __forceinline__ void mbar_wait(unsigned addr, unsigned par) {
    unsigned done;
    do {
        asm volatile("{\n\t.reg .pred p;\n\t"
            "mbarrier.try_wait.parity.acquire.cluster.shared::cta.b64 p, [%1], %2, 0x989680;\n\t"
            "selp.b32 %0, 1, 0, p;\n\t}"
            : "=r"(done) : "r"(addr), "r"(par) : "memory");
    } while (!done);
}
#define CLUSTER_SYNC_() do { \
    asm volatile("barrier.cluster.arrive.aligned;" ::: "memory"); \
    asm volatile("barrier.cluster.wait.aligned;"   ::: "memory"); } while (0)

// =====================================================================
// K0: FPS over 8-CTA clusters, ONE WARP per CTA (32 pts/thread).
// No __syncthreads, no CTA-level reduce: warp redux -> lanes 0..7 push
// the single CTA record to all 8 CTAs (8 records / 192B per iter, same
// traffic as R10) -> tx-barrier wait -> 8-slot max everywhere.
// =====================================================================
extern "C" __global__ void __launch_bounds__(FPS_T, 1) __cluster_dims__(CLU, 1, 1)
k_fps(const float* __restrict__ xyz)
{
    __shared__ float4 sp4[SLICE];        // 16 KB slice {x,y,z,0}
    __shared__ ull    rkey[2][CLU];      // [buf][src] winner keys
    __shared__ ull    rxy [2][CLU];      // packed {x,y}
    __shared__ ull    rz  [2][CLU];      // packed {z,0}
    __shared__ ull    mb[2];             // alternating tx mbarriers

    const int tid  = threadIdx.x;        // == lane
    const unsigned rank = my_ctarank();
    const int b = blockIdx.x / CLU;
    const float* X = xyz + b*3*NPTS;

    for (int i = tid; i < SLICE; i += FPS_T) {
        int gi = (int)rank*SLICE + i;
        sp4[i] = make_float4(X[gi], X[NPTS+gi], X[2*NPTS+gi], 0.f);
    }
    if (tid == 0) {
        mbar_init(smem_u32(&mb[0]), 1);
        mbar_init(smem_u32(&mb[1]), 1);
        if (rank == 0) g_fps[b*NQ] = 0;
    }
    __syncthreads();
    CLUSTER_SYNC_();

    // 32 points/thread -> 16 packed f32x2 pairs; local idx = tid + m*32
    ull px2[PPT/2], py2[PPT/2], pz2[PPT/2]; float dd[PPT];
    #pragma unroll
    for (int j = 0; j < PPT/2; j++) {
        float4 a = sp4[tid + (2*j)*FPS_T];
        float4 c = sp4[tid + (2*j+1)*FPS_T];
        px2[j] = pk2(a.x, c.x); py2[j] = pk2(a.y, c.y); pz2[j] = pk2(a.z, c.z);
        dd[2*j] = 1e10f; dd[2*j+1] = 1e10f;
    }
    float Px = X[0], Py = X[NPTS], Pz = X[2*NPTS];

    // hoisted remote addresses: lane (<8) = target rank
    unsigned rko[2], rxo[2], rzo[2], rmb[2];
    if (tid < CLU) {
        #pragma unroll
        for (int q = 0; q < 2; q++) {
            rko[q] = mapa_u32(smem_u32(&rkey[q][rank]), (unsigned)tid);
            rxo[q] = mapa_u32(smem_u32(&rxy [q][rank]), (unsigned)tid);
            rzo[q] = mapa_u32(smem_u32(&rz  [q][rank]), (unsigned)tid);
            rmb[q] = mapa_u32(smem_u32(&mb[q]),          (unsigned)tid);
        }
    }
    const unsigned mbA = smem_u32(&mb[0]), mbB = smem_u32(&mb[1]);
    int parA = 0, parB = 0;

    for (int it = 1; it < NQ; ++it) {
        const int ib = (it - 1) & 1;
        if (tid == 0) mbar_expect_tx(ib ? mbB : mbA, 24u * CLU);
        // ---- local distance update + per-thread best (exact non-fused) ----
        ull nPx = pk2(-Px,-Px), nPy = pk2(-Py,-Py), nPz = pk2(-Pz,-Pz);
        float bv = -1.f; int bm = 0;
        #pragma unroll
        for (int j = 0; j < PPT/2; j++) {
            ull dx = add2(px2[j], nPx);
            ull dy = add2(py2[j], nPy);
            ull dz = add2(pz2[j], nPz);
            ull s  = add2(add2(mul2(dx,dx), mul2(dy,dy)), mul2(dz,dz));
            float lo, hi; upk2(lo, hi, s);
            float n0 = fminf(dd[2*j],   lo); dd[2*j]   = n0;
            float n1 = fminf(dd[2*j+1], hi); dd[2*j+1] = n1;
            if (n0 > bv) { bv = n0; bm = 2*j; }
            if (n1 > bv) { bv = n1; bm = 2*j+1; }
        }
        int gidx = (int)rank*SLICE + tid + bm*FPS_T;
        // ---- warp argmax, branchless min-index tie-break ----
        unsigned vb  = __float_as_uint(bv);
        unsigned mx  = __reduce_max_sync(0xffffffffu, vb);
        unsigned cnd = (vb == mx) ? (unsigned)gidx : 0x7fffffffu;
        unsigned wix = __reduce_min_sync(0xffffffffu, cnd);
        // ---- direct publish of the CTA record to all 8 CTAs ----
        if (tid < CLU) {
            ull k = ((ull)mx << 32) | (ull)(0xFFFFFFFFu - wix);
            float4 w = sp4[(int)wix - (int)rank*SLICE];   // warp-uniform broadcast
            st_async_u64(rko[ib], k,             rmb[ib]);
            st_async_u64(rxo[ib], pk2(w.x, w.y), rmb[ib]);
            st_async_u64(rzo[ib], pk2(w.z, 0.f), rmb[ib]);
        }
        // ---- wait 8 records (192B tx), global 8-slot argmax ----
        if (ib == 0) { mbar_wait(mbA, (unsigned)parA); parA ^= 1; }
        else         { mbar_wait(mbB, (unsigned)parB); parB ^= 1; }
        {
            const ulonglong2* rv = (const ulonglong2*)rkey[ib];
            ull k = 0; int s = 0;
            #pragma unroll
            for (int i = 0; i < CLU/2; i++) {
                ulonglong2 p2 = rv[i];
                if (p2.x > k) { k = p2.x; s = 2*i; }
                if (p2.y > k) { k = p2.y; s = 2*i+1; }
            }
            float zx; upk2(Px, Py, rxy[ib][s]);
            upk2(Pz, zx, rz[ib][s]);
            if (rank == 0 && tid == 0)
                g_fps[b*NQ + it] = (int)(0xFFFFFFFFu - (unsigned)k);
        }
    }
    CLUSTER_SYNC_();
}

// =====================================================================
// K1: aux — xyz4 build (+ stat zero) and points transpose
// =====================================================================
extern "C" __global__ void __launch_bounds__(1024)
k_aux(const float* __restrict__ xyz, const float* __restrict__ pts)
{
    extern __shared__ float sm[];
    const int tid = threadIdx.x;
    const int bid = blockIdx.x;
    if (bid < 64) {
        int b = bid >> 3;
        int i = ((bid & 7) << 10) + tid;
        const float* X = xyz + b*3*NPTS;
        float x = X[i], y = X[NPTS+i], z = X[2*NPTS+i];
        g_xyz4[b*NPTS + i] = make_float4(x, y, z, sq3(x,y,z));
        if (bid == 0 && tid < 64) {
            g_sum1[tid]=0.0; g_sq1[tid]=0.0; g_sum2[tid]=0.0; g_sq2[tid]=0.0;
        }
    } else {
        int id = bid - 64;
        int b  = id >> 5;
        int nb = (id & 31) << 8;
        float* tile = sm;                          // [256][68]
        const float* Pp = pts + (size_t)b*64*NPTS;
        for (int i = tid; i < 64*256; i += 1024) {
            int c = i >> 8, n = i & 255;
            tile[n*68 + c] = Pp[c*NPTS + nb + n];
        }
        __syncthreads();
        for (int i = tid; i < 256*16; i += 1024) {
            int n = i >> 4, c4 = (i & 15) << 2;
            float4 v = *(const float4*)&tile[n*68 + c4];
            *(float4*)&g_ptsT[((size_t)(b*NPTS + nb + n))*64 + c4] = v;
        }
    }
}

// =====================================================================
// K2: KNN 16-NN, split-scan + lexicographic merge
// =====================================================================
extern "C" __global__ void __launch_bounds__(256)
k_knn(float* __restrict__ out)
{
    extern __shared__ float smraw[];
    float4* sp = (float4*)smraw;                 // [8192] = 128 KB
    float*  md = (float*)(sp + NPTS);            // [16][256]
    int*    mi = (int*)(md + 16*256);            // [16][256]
    const int tid  = threadIdx.x;
    const int qi   = tid & 127;
    const int half = tid >> 7;
    const int b = blockIdx.x >> 4;
    const int q = ((blockIdx.x & 15) << 7) + qi;

    for (int i = tid; i < NPTS; i += 256)
        sp[i] = g_xyz4[b*NPTS + i];
    __syncthreads();

    const int i0 = g_fps[b*NQ + q];
    float4 qv = sp[i0];
    if (half == 0) {
        g_qxyz[b*NQ + q] = qv;
        out[b*3*NQ + q]        = qv.x;
        out[b*3*NQ + NQ + q]   = qv.y;
        out[b*3*NQ + 2*NQ + q] = qv.z;
    }

    float nd[16]; int ni[16];
    #pragma unroll
    for (int j = 0; j < 16; j++) { nd[j] = 3.0e38f; ni[j] = 0; }
    const int beg = half << 12, fin = beg + 4096;
    #pragma unroll 4
    for (int i = beg; i < fin; i++) {
        float4 p = sp[i];
        float dot = __fadd_rn(__fadd_rn(__fmul_rn(p.x,qv.x), __fmul_rn(p.y,qv.y)),
                              __fmul_rn(p.z,qv.z));
        float d = __fsub_rn(__fadd_rn(qv.w, p.w), __fmul_rn(2.0f, dot));
        if (d < nd[15]) {
            nd[15] = d; ni[15] = i;
            #pragma unroll
            for (int j = 15; j > 0; --j) {
                if (nd[j] < nd[j-1]) {
                    float td = nd[j]; nd[j] = nd[j-1]; nd[j-1] = td;
                    int   ti = ni[j]; ni[j] = ni[j-1]; ni[j-1] = ti;
                }
            }
        }
    }
    #pragma unroll
    for (int j = 0; j < 16; j++) { md[j*256 + tid] = nd[j]; mi[j*256 + tid] = ni[j]; }
    __syncthreads();
    if (half == 0) {
        const int base = (b*NQ + q)*KNN_K;
        int ia = 0, ic = 0;
        #pragma unroll
        for (int j = 0; j < 16; j++) {
            float da = (ia < 16) ? md[ia*256 + qi]       : 3.4e38f;
            float dc = (ic < 16) ? md[ic*256 + 128 + qi] : 3.4e38f;
            if (da <= dc) { g_knn[base + j] = mi[ia*256 + qi];       ia++; }
            else          { g_knn[base + j] = mi[ic*256 + 128 + qi]; ic++; }
        }
    }
}

// =====================================================================
// K3: layer1 GEMM (64 x 67), 256-sample tiles (R10 config) + BN1 stats
// =====================================================================
extern "C" __global__ void __launch_bounds__(256, 2)
k_l1(const float* __restrict__ W1, const float* __restrict__ b1)
{
    extern __shared__ float sm[];
    float* sW  = sm;            // 67*64  = 4288
    float* sF  = sW + 4288;     // 67*256 = 17152
    float* shS = sF + 17152;    // 64
    float* shQ = shS + 64;      // 64
    const int tid = threadIdx.x, blk = blockIdx.x;

    for (int i = tid; i < 4288; i += 256)
        sW[i] = W1[(i & 63)*67 + (i >> 6)];
    if (tid < 64) { shS[tid] = 0.f; shQ[tid] = 0.f; }
    {
        int S = blk*256 + tid;
        int b = S >> 15; int q = (S & 32767) >> 4;
        int n = g_knn[S];
        float4 qv = g_qxyz[b*NQ + q];
        float4 pv = g_xyz4[b*NPTS + n];
        sF[tid]       = pv.x - qv.x;
        sF[256 + tid] = pv.y - qv.y;
        sF[512 + tid] = pv.z - qv.z;
        const float4* pr = (const float4*)&g_ptsT[(size_t)(b*NPTS + n)*64];
        #pragma unroll
        for (int j = 0; j < 16; j++) {
            float4 v = pr[j];
            int c = 3 + (j << 2);
            sF[(c+0)*256+tid]=v.x; sF[(c+1)*256+tid]=v.y;
            sF[(c+2)*256+tid]=v.z; sF[(c+3)*256+tid]=v.w;
        }
    }
    __syncthreads();

    const int tc = tid & 7, tr = tid >> 3;
    ull acc2[8][4];
    #pragma unroll
    for (int ci = 0; ci < 8; ci++) {
        float bb = __ldg(&b1[(tc<<3)+ci]);
        ull bp = pk2(bb, bb);
        #pragma unroll
        for (int p = 0; p < 4; p++) acc2[ci][p] = bp;
    }
    #pragma unroll 1
    for (int k = 0; k < 67; k++) {
        float4 wa = *(float4*)&sW[k*64 + (tc<<3)];
        float4 wb = *(float4*)&sW[k*64 + (tc<<3) + 4];
        float4 fa = *(float4*)&sF[k*256 + (tr<<3)];
        float4 fb = *(float4*)&sF[k*256 + (tr<<3) + 4];
        ull f2[4] = {pk2(fa.x,fa.y), pk2(fa.z,fa.w), pk2(fb.x,fb.y), pk2(fb.z,fb.w)};
        float w[8] = {wa.x,wa.y,wa.z,wa.w,wb.x,wb.y,wb.z,wb.w};
        #pragma unroll
        for (int ci = 0; ci < 8; ci++) {
            ull wp = pk2(w[ci], w[ci]);
            #pragma unroll
            for (int p = 0; p < 4; p++)
                acc2[ci][p] = fma2(wp, f2[p], acc2[ci][p]);
        }
    }
    float acc[8][8];
    #pragma unroll
    for (int ci = 0; ci < 8; ci++)
        #pragma unroll
        for (int p = 0; p < 4; p++)
            upk2(acc[ci][2*p], acc[ci][2*p+1], acc2[ci][p]);

    #pragma unroll
    for (int ci = 0; ci < 8; ci++) {
        float s = 0.f, qq = 0.f;
        #pragma unroll
        for (int si = 0; si < 8; si++) { float v = acc[ci][si]; s += v; qq = fmaf(v,v,qq); }
        atomicAdd(&shS[(tc<<3)+ci], s);
        atomicAdd(&shQ[(tc<<3)+ci], qq);
    }
    #pragma unroll
    for (int si = 0; si < 8; si++) {
        size_t So = (size_t)(blk*256 + (tr<<3) + si);
        *(float4*)&g_Y1[So*64 + (tc<<3)]     = make_float4(acc[0][si],acc[1][si],acc[2][si],acc[3][si]);
        *(float4*)&g_Y1[So*64 + (tc<<3) + 4] = make_float4(acc[4][si],acc[5][si],acc[6][si],acc[7][si]);
    }
    __syncthreads();
    if (tid < 64) {
        atomicAdd(&g_sum1[tid], (double)shS[tid]);
        atomicAdd(&g_sq1[tid],  (double)shQ[tid]);
    }
}

// =====================================================================
// BN finalize
// =====================================================================
extern "C" __global__ void k_fin(const float* __restrict__ g,
                                 const float* __restrict__ be, int layer)
{
    int c = threadIdx.x;
    double su = layer ? g_sum2[c] : g_sum1[c];
    double sq = layer ? g_sq2[c]  : g_sq1[c];
    double mean = su * (1.0/262144.0);
    double var  = sq * (1.0/262144.0) - mean*mean;
    double inv  = 1.0 / sqrt(var + 1e-5);
    float sc = (float)((double)g[c] * inv);
    float sh = (float)((double)be[c] - mean * (double)g[c] * inv);
    if (layer) { g_s2[c]=sc; g_t2[c]=sh; } else { g_s1[c]=sc; g_t1[c]=sh; }
}

// =====================================================================
// K5: layer2 GEMM (64 x 64), 256-sample tiles (R10), BN1 fused, + BN2 stats
// =====================================================================
extern "C" __global__ void __launch_bounds__(256, 2)
k_l2(const float* __restrict__ W2, const float* __restrict__ b2)
{
    extern __shared__ float sm[];
    float* sW  = sm;            // 4096
    float* sH  = sW + 4096;     // 16384
    float* ss  = sH + 16384;    // 64
    float* st  = ss + 64;       // 64
    float* shS = st + 64;       // 64
    float* shQ = shS + 64;      // 64
    const int tid = threadIdx.x, blk = blockIdx.x;

    for (int i = tid; i < 4096; i += 256)
        sW[i] = W2[(i & 63)*64 + (i >> 6)];
    if (tid < 64) { ss[tid]=g_s1[tid]; st[tid]=g_t1[tid]; shS[tid]=0.f; shQ[tid]=0.f; }
    __syncthreads();
    {
        int S = blk*256 + tid;
        const float4* yr = (const float4*)&g_Y1[(size_t)S*64];
        #pragma unroll
        for (int j = 0; j < 16; j++) {
            float4 y = yr[j];
            float4 sv = *(float4*)&ss[j<<2];
            float4 tv = *(float4*)&st[j<<2];
            int c = j << 2;
            sH[(c+0)*256+tid] = fmaxf(fmaf(y.x,sv.x,tv.x),0.f);
            sH[(c+1)*256+tid] = fmaxf(fmaf(y.y,sv.y,tv.y),0.f);
            sH[(c+2)*256+tid] = fmaxf(fmaf(y.z,sv.z,tv.z),0.f);
            sH[(c+3)*256+tid] = fmaxf(fmaf(y.w,sv.w,tv.w),0.f);
        }
    }
    __syncthreads();

    const int tc = tid & 7, tr = tid >> 3;
    ull acc2[8][4];
    #pragma unroll
    for (int ci = 0; ci < 8; ci++) {
        float bb = __ldg(&b2[(tc<<3)+ci]);
        ull bp = pk2(bb, bb);
        #pragma unroll
        for (int p = 0; p < 4; p++) acc2[ci][p] = bp;
    }
    #pragma unroll 1
    for (int k = 0; k < 64; k++) {
        float4 wa = *(float4*)&sW[k*64 + (tc<<3)];
        float4 wb = *(float4*)&sW[k*64 + (tc<<3) + 4];
        float4 fa = *(float4*)&sH[k*256 + (tr<<3)];
        float4 fb = *(float4*)&sH[k*256 + (tr<<3) + 4];
        ull f2[4] = {pk2(fa.x,fa.y), pk2(fa.z,fa.w), pk2(fb.x,fb.y), pk2(fb.z,fb.w)};
        float w[8] = {wa.x,wa.y,wa.z,wa.w,wb.x,wb.y,wb.z,wb.w};
        #pragma unroll
        for (int ci = 0; ci < 8; ci++) {
            ull wp = pk2(w[ci], w[ci]);
            #pragma unroll
            for (int p = 0; p < 4; p++)
                acc2[ci][p] = fma2(wp, f2[p], acc2[ci][p]);
        }
    }
    float acc[8][8];
    #pragma unroll
    for (int ci = 0; ci < 8; ci++)
        #pragma unroll
        for (int p = 0; p < 4; p++)
            upk2(acc[ci][2*p], acc[ci][2*p+1], acc2[ci][p]);

    #pragma unroll
    for (int ci = 0; ci < 8; ci++) {
        float s = 0.f, qq = 0.f;
        #pragma unroll
        for (int si = 0; si < 8; si++) { float v = acc[ci][si]; s += v; qq = fmaf(v,v,qq); }
        atomicAdd(&shS[(tc<<3)+ci], s);
        atomicAdd(&shQ[(tc<<3)+ci], qq);
    }
    #pragma unroll
    for (int si = 0; si < 8; si++) {
        size_t So = (size_t)(blk*256 + (tr<<3) + si);
        *(float4*)&g_Y2[So*64 + (tc<<3)]     = make_float4(acc[0][si],acc[1][si],acc[2][si],acc[3][si]);
        *(float4*)&g_Y2[So*64 + (tc<<3) + 4] = make_float4(acc[4][si],acc[5][si],acc[6][si],acc[7][si]);
    }
    __syncthreads();
    if (tid < 64) {
        atomicAdd(&g_sum2[tid], (double)shS[tid]);
        atomicAdd(&g_sq2[tid],  (double)shQ[tid]);
    }
}

// =====================================================================
// K7: layer3 GEMM (128 x 64), 256-sample tiles (R10), BN2 fused,
//     fused max-pool over K=16 neighbors, writes new_feat.
// =====================================================================
extern "C" __global__ void __launch_bounds__(256, 2)
k_l3(const float* __restrict__ W3, const float* __restrict__ b3,
     float* __restrict__ out)
{
    extern __shared__ float sm[];
    float* sW = sm;             // 64*128 = 8192 (layout [k][o])
    float* sH = sW + 8192;      // 64*256 = 16384
    float* ss = sH + 16384;     // 64
    float* st = ss + 64;        // 64
    const int tid = threadIdx.x, blk = blockIdx.x;

    for (int i = tid; i < 8192; i += 256)
        sW[i] = W3[(i & 127)*64 + (i >> 7)];
    if (tid < 64) { ss[tid]=g_s2[tid]; st[tid]=g_t2[tid]; }
    __syncthreads();
    {
        int S = blk*256 + tid;
        const float4* yr = (const float4*)&g_Y2[(size_t)S*64];
        #pragma unroll
        for (int j = 0; j < 16; j++) {
            float4 y = yr[j];
            float4 sv = *(float4*)&ss[j<<2];
            float4 tv = *(float4*)&st[j<<2];
            int c = j << 2;
            sH[(c+0)*256+tid] = fmaxf(fmaf(y.x,sv.x,tv.x),0.f);
            sH[(c+1)*256+tid] = fmaxf(fmaf(y.y,sv.y,tv.y),0.f);
            sH[(c+2)*256+tid] = fmaxf(fmaf(y.z,sv.z,tv.z),0.f);
            sH[(c+3)*256+tid] = fmaxf(fmaf(y.w,sv.w,tv.w),0.f);
        }
    }
    __syncthreads();

    const int tc = tid & 7, tr = tid >> 3;        // tr in [0,32): 8 samples each
    const int q_local = tr >> 1;                   // 16 queries per block
    const int qg = blk*16 + q_local;
    const int b = qg >> 11, qq = qg & 2047;
    float* feat = out + OXYZ + (size_t)b*128*NQ;

    for (int h = 0; h < 2; h++) {
        ull acc2[8][4];
        #pragma unroll
        for (int ci = 0; ci < 8; ci++) {
            float bb = __ldg(&b3[h*64 + (tc<<3)+ci]);
            ull bp = pk2(bb, bb);
            #pragma unroll
            for (int p = 0; p < 4; p++) acc2[ci][p] = bp;
        }
        #pragma unroll 1
        for (int k = 0; k < 64; k++) {
            float4 wa = *(float4*)&sW[k*128 + h*64 + (tc<<3)];
            float4 wb = *(float4*)&sW[k*128 + h*64 + (tc<<3) + 4];
            float4 fa = *(float4*)&sH[k*256 + (tr<<3)];
            float4 fb = *(float4*)&sH[k*256 + (tr<<3) + 4];
            ull f2[4] = {pk2(fa.x,fa.y), pk2(fa.z,fa.w), pk2(fb.x,fb.y), pk2(fb.z,fb.w)};
            float w[8] = {wa.x,wa.y,wa.z,wa.w,wb.x,wb.y,wb.z,wb.w};
            #pragma unroll
            for (int ci = 0; ci < 8; ci++) {
                ull wp = pk2(w[ci], w[ci]);
                #pragma unroll
                for (int p = 0; p < 4; p++)
                    acc2[ci][p] = fma2(wp, f2[p], acc2[ci][p]);
            }
        }
        #pragma unroll
        for (int ci = 0; ci < 8; ci++) {
            float a0, a1, m;
            upk2(a0, a1, acc2[ci][0]); m = fmaxf(a0, a1);
            #pragma unroll
            for (int p = 1; p < 4; p++) {
                upk2(a0, a1, acc2[ci][p]);
                m = fmaxf(m, fmaxf(a0, a1));
            }
            float om = __shfl_xor_sync(0xffffffffu, m, 8);
            m = fmaxf(m, om);
            if ((tr & 1) == 0)
                feat[(h*64 + (tc<<3) + ci)*NQ + qq] = m;
        }
    }
}

// =====================================================================
extern "C" void kernel_launch(void* const* d_in, const int* in_sizes, int n_in,
                              void* d_out, int out_size)
{
    const float* xyz = (const float*)d_in[0];
    const float* pts = (const float*)d_in[1];
    const float* W1  = (const float*)d_in[2];
    const float* b1  = (const float*)d_in[3];
    const float* g1  = (const float*)d_in[4];
    const float* be1 = (const float*)d_in[5];
    const float* W2  = (const float*)d_in[6];
    const float* b2  = (const float*)d_in[7];
    const float* g2  = (const float*)d_in[8];
    const float* be2 = (const float*)d_in[9];
    const float* W3  = (const float*)d_in[10];
    const float* b3  = (const float*)d_in[11];
    float* out = (float*)d_out;

    cudaFuncSetAttribute(k_aux, cudaFuncAttributeMaxDynamicSharedMemorySize, 69632);
    cudaFuncSetAttribute(k_knn, cudaFuncAttributeMaxDynamicSharedMemorySize, 163840);
    cudaFuncSetAttribute(k_l1,  cudaFuncAttributeMaxDynamicSharedMemorySize, 86272);
    cudaFuncSetAttribute(k_l2,  cudaFuncAttributeMaxDynamicSharedMemorySize, 82944);
    cudaFuncSetAttribute(k_l3,  cudaFuncAttributeMaxDynamicSharedMemorySize, 98816);

    k_fps<<<NB*CLU, FPS_T>>>(xyz);
    k_aux<<<320, 1024, 69632>>>(xyz, pts);
    k_knn<<<128, 256, 163840>>>(out);
    k_l1 <<<1024, 256, 86272>>>(W1, b1);
    k_fin<<<1, 64>>>(g1, be1, 0);
    k_l2 <<<1024, 256, 82944>>>(W2, b2);
    k_fin<<<1, 64>>>(g2, be2, 1);
    k_l3 <<<1024, 256, 98816>>>(W3, b3, out);
}

// round 16
// speedup vs baseline: 1.4289x; 1.0930x over previous
#include <cuda_runtime.h>
#include <math.h>

#define NB     8
#define NPTS   8192
#define NQ     2048
#define KNN_K  16
#define NSAMP  (NB*NQ*KNN_K)        /* 262144 */
#define OXYZ   (NB*3*NQ)            /* 49152  */

#define CLU    8                    /* cluster size for FPS */
#define FPS_T  128                  /* threads per FPS CTA (R10 config) */
#define SLICE  (NPTS/CLU)           /* 1024 points per CTA  */

// ---------------- static scratch (no allocations) ----------------
__device__ int    g_fps[NB*NQ];
__device__ int    g_knn[NSAMP];
__device__ float4 g_xyz4[NB*NPTS];                 // {x,y,z,|p|^2}
__device__ float4 g_qxyz[NB*NQ];                   // selected query points
__device__ float  g_ptsT[(size_t)NB*NPTS*64];      // points transposed (B,N,64)
__device__ float  g_Y1[(size_t)NSAMP*64];
__device__ float  g_Y2[(size_t)NSAMP*64];
__device__ double g_sum1[64], g_sq1[64], g_sum2[64], g_sq2[64];
__device__ float  g_s1[64], g_t1[64], g_s2[64], g_t2[64];

typedef unsigned long long ull;

// -------- packed f32x2 helpers --------
__device__ __forceinline__ ull pk2(float a, float b) {
    ull r; asm("mov.b64 %0, {%1, %2};" : "=l"(r) : "f"(a), "f"(b)); return r;
}
__device__ __forceinline__ void upk2(float& a, float& b, ull r) {
    asm("mov.b64 {%0, %1}, %2;" : "=f"(a), "=f"(b) : "l"(r));
}
__device__ __forceinline__ ull add2(ull a, ull b) {
    ull r; asm("add.rn.f32x2 %0, %1, %2;" : "=l"(r) : "l"(a), "l"(b)); return r;
}
__device__ __forceinline__ ull mul2(ull a, ull b) {
    ull r; asm("mul.rn.f32x2 %0, %1, %2;" : "=l"(r) : "l"(a), "l"(b)); return r;
}
__device__ __forceinline__ ull fma2(ull a, ull b, ull c) {
    ull r; asm("fma.rn.f32x2 %0, %1, %2, %3;" : "=l"(r) : "l"(a), "l"(b), "l"(c)); return r;
}
__device__ __forceinline__ float sq3(float a, float b, float c) {
    return __fadd_rn(__fadd_rn(__fmul_rn(a,a), __fmul_rn(b,b)), __fmul_rn(c,c));
}

// -------- cluster / mbarrier helpers --------
__device__ __forceinline__ unsigned smem_u32(const void* p) {
    return (unsigned)__cvta_generic_to_shared(p);
}
__device__ __forceinline__ unsigned my_ctarank() {
    unsigned r; asm("mov.u32 %0, %%cluster_ctarank;" : "=r"(r)); return r;
}
__device__ __forceinline__ unsigned mapa_u32(unsigned addr, unsigned rank) {
    unsigned r; asm("mapa.shared::cluster.u32 %0, %1, %2;" : "=r"(r) : "r"(addr), "r"(rank));
    return r;
}
__device__ __forceinline__ void mbar_init(unsigned addr, unsigned cnt) {
    asm volatile("mbarrier.init.shared.b64 [%0], %1;" :: "r"(addr), "r"(cnt) : "memory");
}
__device__ __forceinline__ void st_async_u64(unsigned raddr, ull v, unsigned rmbar) {
    asm volatile("st.async.weak.shared::cluster.mbarrier::complete_tx::bytes.b64 [%0], %1, [%2];"
                 :: "r"(raddr), "l"(v), "r"(rmbar) : "memory");
}
__device__ __forceinline__ void mbar_expect_tx(unsigned addr, unsigned bytes) {
    asm volatile("mbarrier.arrive.expect_tx.shared::cta.b64 _, [%0], %1;"
                 :: "r"(addr), "r"(bytes) : "memory");
}
__device__ __forceinline__ void mbar_wait(unsigned addr, unsigned par) {
    unsigned done;
    do {
        asm volatile("{\n\t.reg .pred p;\n\t"
            "mbarrier.try_wait.parity.acquire.cluster.shared::cta.b64 p, [%1], %2, 0x989680;\n\t"
            "selp.b32 %0, 1, 0, p;\n\t}"
            : "=r"(done) : "r"(addr), "r"(par) : "memory");
    } while (!done);
}
#define CLUSTER_SYNC_() do { \
    asm volatile("barrier.cluster.arrive.aligned;" ::: "memory"); \
    asm volatile("barrier.cluster.wait.aligned;"   ::: "memory"); } while (0)

// =====================================================================
// K0: FPS — exact R10 configuration (proven fastest: ~1205us).
// =====================================================================
extern "C" __global__ void __launch_bounds__(FPS_T, 1) __cluster_dims__(CLU, 1, 1)
k_fps(const float* __restrict__ xyz)
{
    __shared__ float4 sp4[SLICE];        // 16 KB slice {x,y,z,0}
    __shared__ ull    wslot[4];          // per-warp winners
    __shared__ ull    rkey[2][CLU];      // [buf][src] winner keys
    __shared__ ull    rxy [2][CLU];      // packed {x,y}
    __shared__ ull    rz  [2][CLU];      // packed {z,0}
    __shared__ ull    mb[2];             // alternating tx mbarriers

    const int tid  = threadIdx.x;
    const int lane = tid & 31, wid = tid >> 5;
    const unsigned rank = my_ctarank();
    const int b = blockIdx.x / CLU;
    const float* X = xyz + b*3*NPTS;

    for (int i = tid; i < SLICE; i += FPS_T) {
        int gi = (int)rank*SLICE + i;
        sp4[i] = make_float4(X[gi], X[NPTS+gi], X[2*NPTS+gi], 0.f);
    }
    if (tid == 0) {
        mbar_init(smem_u32(&mb[0]), 1);
        mbar_init(smem_u32(&mb[1]), 1);
        if (rank == 0) g_fps[b*NQ] = 0;
    }
    __syncthreads();
    CLUSTER_SYNC_();

    ull px2[4], py2[4], pz2[4]; float dd[8];
    #pragma unroll
    for (int j = 0; j < 4; j++) {
        float4 a = sp4[tid + (2*j)*FPS_T];
        float4 c = sp4[tid + (2*j+1)*FPS_T];
        px2[j] = pk2(a.x, c.x); py2[j] = pk2(a.y, c.y); pz2[j] = pk2(a.z, c.z);
        dd[2*j] = 1e10f; dd[2*j+1] = 1e10f;
    }
    float Px = X[0], Py = X[NPTS], Pz = X[2*NPTS];

    unsigned rko[2], rxo[2], rzo[2], rmb[2];
    if (wid == 0 && lane < CLU) {
        #pragma unroll
        for (int q = 0; q < 2; q++) {
            rko[q] = mapa_u32(smem_u32(&rkey[q][rank]), (unsigned)lane);
            rxo[q] = mapa_u32(smem_u32(&rxy [q][rank]), (unsigned)lane);
            rzo[q] = mapa_u32(smem_u32(&rz  [q][rank]), (unsigned)lane);
            rmb[q] = mapa_u32(smem_u32(&mb[q]),          (unsigned)lane);
        }
    }
    const unsigned mbA = smem_u32(&mb[0]), mbB = smem_u32(&mb[1]);
    int parA = 0, parB = 0;

    for (int it = 1; it < NQ; ++it) {
        const int ib = (it - 1) & 1;
        if (tid == 0) mbar_expect_tx(ib ? mbB : mbA, 24u * CLU);
        ull nPx = pk2(-Px,-Px), nPy = pk2(-Py,-Py), nPz = pk2(-Pz,-Pz);
        float bv = -1.f; int bm = 0;
        #pragma unroll
        for (int j = 0; j < 4; j++) {
            ull dx = add2(px2[j], nPx);
            ull dy = add2(py2[j], nPy);
            ull dz = add2(pz2[j], nPz);
            ull s  = add2(add2(mul2(dx,dx), mul2(dy,dy)), mul2(dz,dz));
            float lo, hi; upk2(lo, hi, s);
            float n0 = fminf(dd[2*j],   lo); dd[2*j]   = n0;
            float n1 = fminf(dd[2*j+1], hi); dd[2*j+1] = n1;
            if (n0 > bv) { bv = n0; bm = 2*j; }
            if (n1 > bv) { bv = n1; bm = 2*j+1; }
        }
        int gidx = (int)rank*SLICE + tid + bm*FPS_T;
        unsigned vb  = __float_as_uint(bv);
        unsigned mx  = __reduce_max_sync(0xffffffffu, vb);
        unsigned cnd = (vb == mx) ? (unsigned)gidx : 0x7fffffffu;
        unsigned wix = __reduce_min_sync(0xffffffffu, cnd);
        if (lane == 0)
            wslot[wid] = ((ull)mx << 32) | (ull)(0xFFFFFFFFu - wix);
        __syncthreads();
        if (wid == 0 && lane < CLU) {
            ull k0 = wslot[0], k1 = wslot[1], k2 = wslot[2], k3 = wslot[3];
            ull ka = k0 > k1 ? k0 : k1;
            ull kb = k2 > k3 ? k2 : k3;
            ull k  = ka > kb ? ka : kb;
            int lidx = (int)(0xFFFFFFFFu - (unsigned)k) - (int)rank*SLICE;
            float4 w = sp4[lidx];
            st_async_u64(rko[ib], k,             rmb[ib]);
            st_async_u64(rxo[ib], pk2(w.x, w.y), rmb[ib]);
            st_async_u64(rzo[ib], pk2(w.z, 0.f), rmb[ib]);
        }
        if (ib == 0) { mbar_wait(mbA, (unsigned)parA); parA ^= 1; }
        else         { mbar_wait(mbB, (unsigned)parB); parB ^= 1; }
        {
            const ulonglong2* rv = (const ulonglong2*)rkey[ib];
            ull k = 0; int s = 0;
            #pragma unroll
            for (int i = 0; i < CLU/2; i++) {
                ulonglong2 p2 = rv[i];
                if (p2.x > k) { k = p2.x; s = 2*i; }
                if (p2.y > k) { k = p2.y; s = 2*i+1; }
            }
            float zx; upk2(Px, Py, rxy[ib][s]);
            upk2(Pz, zx, rz[ib][s]);
            if (rank == 0 && tid == 0)
                g_fps[b*NQ + it] = (int)(0xFFFFFFFFu - (unsigned)k);
        }
    }
    CLUSTER_SYNC_();
}

// =====================================================================
// K1: aux — xyz4 build (+ stat zero) and points transpose
// =====================================================================
extern "C" __global__ void __launch_bounds__(1024)
k_aux(const float* __restrict__ xyz, const float* __restrict__ pts)
{
    extern __shared__ float sm[];
    const int tid = threadIdx.x;
    const int bid = blockIdx.x;
    if (bid < 64) {
        int b = bid >> 3;
        int i = ((bid & 7) << 10) + tid;
        const float* X = xyz + b*3*NPTS;
        float x = X[i], y = X[NPTS+i], z = X[2*NPTS+i];
        g_xyz4[b*NPTS + i] = make_float4(x, y, z, sq3(x,y,z));
        if (bid == 0 && tid < 64) {
            g_sum1[tid]=0.0; g_sq1[tid]=0.0; g_sum2[tid]=0.0; g_sq2[tid]=0.0;
        }
    } else {
        int id = bid - 64;
        int b  = id >> 5;
        int nb = (id & 31) << 8;
        float* tile = sm;                          // [256][68]
        const float* Pp = pts + (size_t)b*64*NPTS;
        for (int i = tid; i < 64*256; i += 1024) {
            int c = i >> 8, n = i & 255;
            tile[n*68 + c] = Pp[c*NPTS + nb + n];
        }
        __syncthreads();
        for (int i = tid; i < 256*16; i += 1024) {
            int n = i >> 4, c4 = (i & 15) << 2;
            float4 v = *(const float4*)&tile[n*68 + c4];
            *(float4*)&g_ptsT[((size_t)(b*NPTS + nb + n))*64 + c4] = v;
        }
    }
}

// =====================================================================
// K2: KNN 16-NN, split-scan + lexicographic merge
// =====================================================================
extern "C" __global__ void __launch_bounds__(256)
k_knn(float* __restrict__ out)
{
    extern __shared__ float smraw[];
    float4* sp = (float4*)smraw;                 // [8192] = 128 KB
    float*  md = (float*)(sp + NPTS);            // [16][256]
    int*    mi = (int*)(md + 16*256);            // [16][256]
    const int tid  = threadIdx.x;
    const int qi   = tid & 127;
    const int half = tid >> 7;
    const int b = blockIdx.x >> 4;
    const int q = ((blockIdx.x & 15) << 7) + qi;

    for (int i = tid; i < NPTS; i += 256)
        sp[i] = g_xyz4[b*NPTS + i];
    __syncthreads();

    const int i0 = g_fps[b*NQ + q];
    float4 qv = sp[i0];
    if (half == 0) {
        g_qxyz[b*NQ + q] = qv;
        out[b*3*NQ + q]        = qv.x;
        out[b*3*NQ + NQ + q]   = qv.y;
        out[b*3*NQ + 2*NQ + q] = qv.z;
    }

    float nd[16]; int ni[16];
    #pragma unroll
    for (int j = 0; j < 16; j++) { nd[j] = 3.0e38f; ni[j] = 0; }
    const int beg = half << 12, fin = beg + 4096;
    #pragma unroll 4
    for (int i = beg; i < fin; i++) {
        float4 p = sp[i];
        float dot = __fadd_rn(__fadd_rn(__fmul_rn(p.x,qv.x), __fmul_rn(p.y,qv.y)),
                              __fmul_rn(p.z,qv.z));
        float d = __fsub_rn(__fadd_rn(qv.w, p.w), __fmul_rn(2.0f, dot));
        if (d < nd[15]) {
            nd[15] = d; ni[15] = i;
            #pragma unroll
            for (int j = 15; j > 0; --j) {
                if (nd[j] < nd[j-1]) {
                    float td = nd[j]; nd[j] = nd[j-1]; nd[j-1] = td;
                    int   ti = ni[j]; ni[j] = ni[j-1]; ni[j-1] = ti;
                }
            }
        }
    }
    #pragma unroll
    for (int j = 0; j < 16; j++) { md[j*256 + tid] = nd[j]; mi[j*256 + tid] = ni[j]; }
    __syncthreads();
    if (half == 0) {
        const int base = (b*NQ + q)*KNN_K;
        int ia = 0, ic = 0;
        #pragma unroll
        for (int j = 0; j < 16; j++) {
            float da = (ia < 16) ? md[ia*256 + qi]       : 3.4e38f;
            float dc = (ic < 16) ? md[ic*256 + 128 + qi] : 3.4e38f;
            if (da <= dc) { g_knn[base + j] = mi[ia*256 + qi];       ia++; }
            else          { g_knn[base + j] = mi[ic*256 + 128 + qi]; ic++; }
        }
    }
}

// =====================================================================
// K3: layer1 GEMM (64 x 67), 256-sample tiles, 128 threads,
//     8ch x 16samples per thread (2x K-reuse per LDS) + BN1 stats
// =====================================================================
extern "C" __global__ void __launch_bounds__(128, 2)
k_l1(const float* __restrict__ W1, const float* __restrict__ b1)
{
    extern __shared__ float sm[];
    float* sW  = sm;            // 67*64  = 4288
    float* sF  = sW + 4288;     // 67*256 = 17152
    float* shS = sF + 17152;    // 64
    float* shQ = shS + 64;      // 64
    const int tid = threadIdx.x, blk = blockIdx.x;

    for (int i = tid; i < 4288; i += 128)
        sW[i] = W1[(i & 63)*67 + (i >> 6)];
    if (tid < 64) { shS[tid] = 0.f; shQ[tid] = 0.f; }
    #pragma unroll
    for (int rep = 0; rep < 2; rep++) {
        int s = tid + rep*128;
        int S = blk*256 + s;
        int b = S >> 15; int q = (S & 32767) >> 4;
        int n = g_knn[S];
        float4 qv = g_qxyz[b*NQ + q];
        float4 pv = g_xyz4[b*NPTS + n];
        sF[s]       = pv.x - qv.x;
        sF[256 + s] = pv.y - qv.y;
        sF[512 + s] = pv.z - qv.z;
        const float4* pr = (const float4*)&g_ptsT[(size_t)(b*NPTS + n)*64];
        #pragma unroll
        for (int j = 0; j < 16; j++) {
            float4 v = pr[j];
            int c = 3 + (j << 2);
            sF[(c+0)*256+s]=v.x; sF[(c+1)*256+s]=v.y;
            sF[(c+2)*256+s]=v.z; sF[(c+3)*256+s]=v.w;
        }
    }
    __syncthreads();

    const int tc = tid & 7, tr = tid >> 3;   // tr in 0..15, 16 samples each
    ull acc2[8][8];
    #pragma unroll
    for (int ci = 0; ci < 8; ci++) {
        float bb = __ldg(&b1[(tc<<3)+ci]);
        ull bp = pk2(bb, bb);
        #pragma unroll
        for (int p = 0; p < 8; p++) acc2[ci][p] = bp;
    }
    #pragma unroll 1
    for (int k = 0; k < 67; k++) {
        float4 wa = *(float4*)&sW[k*64 + (tc<<3)];
        float4 wb = *(float4*)&sW[k*64 + (tc<<3) + 4];
        const float* fb = &sF[k*256 + (tr<<4)];
        float4 f0 = *(float4*)&fb[0];
        float4 f1 = *(float4*)&fb[4];
        float4 f2_ = *(float4*)&fb[8];
        float4 f3 = *(float4*)&fb[12];
        ull f2[8] = {pk2(f0.x,f0.y), pk2(f0.z,f0.w), pk2(f1.x,f1.y), pk2(f1.z,f1.w),
                     pk2(f2_.x,f2_.y), pk2(f2_.z,f2_.w), pk2(f3.x,f3.y), pk2(f3.z,f3.w)};
        float w[8] = {wa.x,wa.y,wa.z,wa.w,wb.x,wb.y,wb.z,wb.w};
        #pragma unroll
        for (int ci = 0; ci < 8; ci++) {
            ull wp = pk2(w[ci], w[ci]);
            #pragma unroll
            for (int p = 0; p < 8; p++)
                acc2[ci][p] = fma2(wp, f2[p], acc2[ci][p]);
        }
    }
    float acc[8][16];
    #pragma unroll
    for (int ci = 0; ci < 8; ci++)
        #pragma unroll
        for (int p = 0; p < 8; p++)
            upk2(acc[ci][2*p], acc[ci][2*p+1], acc2[ci][p]);

    #pragma unroll
    for (int ci = 0; ci < 8; ci++) {
        float s = 0.f, qq = 0.f;
        #pragma unroll
        for (int si = 0; si < 16; si++) { float v = acc[ci][si]; s += v; qq = fmaf(v,v,qq); }
        atomicAdd(&shS[(tc<<3)+ci], s);
        atomicAdd(&shQ[(tc<<3)+ci], qq);
    }
    #pragma unroll
    for (int si = 0; si < 16; si++) {
        size_t So = (size_t)(blk*256 + (tr<<4) + si);
        *(float4*)&g_Y1[So*64 + (tc<<3)]     = make_float4(acc[0][si],acc[1][si],acc[2][si],acc[3][si]);
        *(float4*)&g_Y1[So*64 + (tc<<3) + 4] = make_float4(acc[4][si],acc[5][si],acc[6][si],acc[7][si]);
    }
    __syncthreads();
    if (tid < 64) {
        atomicAdd(&g_sum1[tid], (double)shS[tid]);
        atomicAdd(&g_sq1[tid],  (double)shQ[tid]);
    }
}

// =====================================================================
// BN finalize
// =====================================================================
extern "C" __global__ void k_fin(const float* __restrict__ g,
                                 const float* __restrict__ be, int layer)
{
    int c = threadIdx.x;
    double su = layer ? g_sum2[c] : g_sum1[c];
    double sq = layer ? g_sq2[c]  : g_sq1[c];
    double mean = su * (1.0/262144.0);
    double var  = sq * (1.0/262144.0) - mean*mean;
    double inv  = 1.0 / sqrt(var + 1e-5);
    float sc = (float)((double)g[c] * inv);
    float sh = (float)((double)be[c] - mean * (double)g[c] * inv);
    if (layer) { g_s2[c]=sc; g_t2[c]=sh; } else { g_s1[c]=sc; g_t1[c]=sh; }
}

// =====================================================================
// K5: layer2 GEMM (64 x 64), same 8ch x 16s structure, BN1 fused, + BN2 stats
// =====================================================================
extern "C" __global__ void __launch_bounds__(128, 2)
k_l2(const float* __restrict__ W2, const float* __restrict__ b2)
{
    extern __shared__ float sm[];
    float* sW  = sm;            // 4096
    float* sH  = sW + 4096;     // 16384
    float* ss  = sH + 16384;    // 64
    float* st  = ss + 64;       // 64
    float* shS = st + 64;       // 64
    float* shQ = shS + 64;      // 64
    const int tid = threadIdx.x, blk = blockIdx.x;

    for (int i = tid; i < 4096; i += 128)
        sW[i] = W2[(i & 63)*64 + (i >> 6)];
    if (tid < 64) { ss[tid]=g_s1[tid]; st[tid]=g_t1[tid]; shS[tid]=0.f; shQ[tid]=0.f; }
    __syncthreads();
    #pragma unroll
    for (int rep = 0; rep < 2; rep++) {
        int s = tid + rep*128;
        int S = blk*256 + s;
        const float4* yr = (const float4*)&g_Y1[(size_t)S*64];
        #pragma unroll
        for (int j = 0; j < 16; j++) {
            float4 y = yr[j];
            float4 sv = *(float4*)&ss[j<<2];
            float4 tv = *(float4*)&st[j<<2];
            int c = j << 2;
            sH[(c+0)*256+s] = fmaxf(fmaf(y.x,sv.x,tv.x),0.f);
            sH[(c+1)*256+s] = fmaxf(fmaf(y.y,sv.y,tv.y),0.f);
            sH[(c+2)*256+s] = fmaxf(fmaf(y.z,sv.z,tv.z),0.f);
            sH[(c+3)*256+s] = fmaxf(fmaf(y.w,sv.w,tv.w),0.f);
        }
    }
    __syncthreads();

    const int tc = tid & 7, tr = tid >> 3;
    ull acc2[8][8];
    #pragma unroll
    for (int ci = 0; ci < 8; ci++) {
        float bb = __ldg(&b2[(tc<<3)+ci]);
        ull bp = pk2(bb, bb);
        #pragma unroll
        for (int p = 0; p < 8; p++) acc2[ci][p] = bp;
    }
    #pragma unroll 1
    for (int k = 0; k < 64; k++) {
        float4 wa = *(float4*)&sW[k*64 + (tc<<3)];
        float4 wb = *(float4*)&sW[k*64 + (tc<<3) + 4];
        const float* fb = &sH[k*256 + (tr<<4)];
        float4 f0 = *(float4*)&fb[0];
        float4 f1 = *(float4*)&fb[4];
        float4 f2_ = *(float4*)&fb[8];
        float4 f3 = *(float4*)&fb[12];
        ull f2[8] = {pk2(f0.x,f0.y), pk2(f0.z,f0.w), pk2(f1.x,f1.y), pk2(f1.z,f1.w),
                     pk2(f2_.x,f2_.y), pk2(f2_.z,f2_.w), pk2(f3.x,f3.y), pk2(f3.z,f3.w)};
        float w[8] = {wa.x,wa.y,wa.z,wa.w,wb.x,wb.y,wb.z,wb.w};
        #pragma unroll
        for (int ci = 0; ci < 8; ci++) {
            ull wp = pk2(w[ci], w[ci]);
            #pragma unroll
            for (int p = 0; p < 8; p++)
                acc2[ci][p] = fma2(wp, f2[p], acc2[ci][p]);
        }
    }
    float acc[8][16];
    #pragma unroll
    for (int ci = 0; ci < 8; ci++)
        #pragma unroll
        for (int p = 0; p < 8; p++)
            upk2(acc[ci][2*p], acc[ci][2*p+1], acc2[ci][p]);

    #pragma unroll
    for (int ci = 0; ci < 8; ci++) {
        float s = 0.f, qq = 0.f;
        #pragma unroll
        for (int si = 0; si < 16; si++) { float v = acc[ci][si]; s += v; qq = fmaf(v,v,qq); }
        atomicAdd(&shS[(tc<<3)+ci], s);
        atomicAdd(&shQ[(tc<<3)+ci], qq);
    }
    #pragma unroll
    for (int si = 0; si < 16; si++) {
        size_t So = (size_t)(blk*256 + (tr<<4) + si);
        *(float4*)&g_Y2[So*64 + (tc<<3)]     = make_float4(acc[0][si],acc[1][si],acc[2][si],acc[3][si]);
        *(float4*)&g_Y2[So*64 + (tc<<3) + 4] = make_float4(acc[4][si],acc[5][si],acc[6][si],acc[7][si]);
    }
    __syncthreads();
    if (tid < 64) {
        atomicAdd(&g_sum2[tid], (double)shS[tid]);
        atomicAdd(&g_sq2[tid],  (double)shQ[tid]);
    }
}

// =====================================================================
// K7: layer3 GEMM (128 x 64), 8ch x 16s per thread — one thread = one
//     full query, local max-pool (no shuffles), BN2 fused, writes new_feat.
// =====================================================================
extern "C" __global__ void __launch_bounds__(128, 2)
k_l3(const float* __restrict__ W3, const float* __restrict__ b3,
     float* __restrict__ out)
{
    extern __shared__ float sm[];
    float* sW = sm;             // 64*128 = 8192 (layout [k][o])
    float* sH = sW + 8192;      // 64*256 = 16384
    float* ss = sH + 16384;     // 64
    float* st = ss + 64;        // 64
    const int tid = threadIdx.x, blk = blockIdx.x;

    for (int i = tid; i < 8192; i += 128)
        sW[i] = W3[(i & 127)*64 + (i >> 7)];
    if (tid < 64) { ss[tid]=g_s2[tid]; st[tid]=g_t2[tid]; }
    __syncthreads();
    #pragma unroll
    for (int rep = 0; rep < 2; rep++) {
        int s = tid + rep*128;
        int S = blk*256 + s;
        const float4* yr = (const float4*)&g_Y2[(size_t)S*64];
        #pragma unroll
        for (int j = 0; j < 16; j++) {
            float4 y = yr[j];
            float4 sv = *(float4*)&ss[j<<2];
            float4 tv = *(float4*)&st[j<<2];
            int c = j << 2;
            sH[(c+0)*256+s] = fmaxf(fmaf(y.x,sv.x,tv.x),0.f);
            sH[(c+1)*256+s] = fmaxf(fmaf(y.y,sv.y,tv.y),0.f);
            sH[(c+2)*256+s] = fmaxf(fmaf(y.z,sv.z,tv.z),0.f);
            sH[(c+3)*256+s] = fmaxf(fmaf(y.w,sv.w,tv.w),0.f);
        }
    }
    __syncthreads();

    const int tc = tid & 7, tr = tid >> 3;    // tr = query-in-block (0..15)
    const int qg = blk*16 + tr;
    const int b = qg >> 11, qq = qg & 2047;
    float* feat = out + OXYZ + (size_t)b*128*NQ;

    for (int h = 0; h < 2; h++) {             // two 64-channel halves
        ull acc2[8][8];
        #pragma unroll
        for (int ci = 0; ci < 8; ci++) {
            float bb = __ldg(&b3[h*64 + (tc<<3)+ci]);
            ull bp = pk2(bb, bb);
            #pragma unroll
            for (int p = 0; p < 8; p++) acc2[ci][p] = bp;
        }
        #pragma unroll 1
        for (int k = 0; k < 64; k++) {
            float4 wa = *(float4*)&sW[k*128 + h*64 + (tc<<3)];
            float4 wb = *(float4*)&sW[k*128 + h*64 + (tc<<3) + 4];
            const float* fb = &sH[k*256 + (tr<<4)];
            float4 f0 = *(float4*)&fb[0];
            float4 f1 = *(float4*)&fb[4];
            float4 f2_ = *(float4*)&fb[8];
            float4 f3 = *(float4*)&fb[12];
            ull f2[8] = {pk2(f0.x,f0.y), pk2(f0.z,f0.w), pk2(f1.x,f1.y), pk2(f1.z,f1.w),
                         pk2(f2_.x,f2_.y), pk2(f2_.z,f2_.w), pk2(f3.x,f3.y), pk2(f3.z,f3.w)};
            float w8[8] = {wa.x,wa.y,wa.z,wa.w,wb.x,wb.y,wb.z,wb.w};
            #pragma unroll
            for (int ci = 0; ci < 8; ci++) {
                ull wp = pk2(w8[ci], w8[ci]);
                #pragma unroll
                for (int p = 0; p < 8; p++)
                    acc2[ci][p] = fma2(wp, f2[p], acc2[ci][p]);
            }
        }
        // local max over the query's 16 neighbors — no shuffles needed
        #pragma unroll
        for (int ci = 0; ci < 8; ci++) {
            float a0, a1, m = -3.4e38f;
            #pragma unroll
            for (int p = 0; p < 8; p++) {
                upk2(a0, a1, acc2[ci][p]);
                m = fmaxf(m, fmaxf(a0, a1));
            }
            feat[(h*64 + (tc<<3) + ci)*NQ + qq] = m;
        }
    }
}

// =====================================================================
extern "C" void kernel_launch(void* const* d_in, const int* in_sizes, int n_in,
                              void* d_out, int out_size)
{
    const float* xyz = (const float*)d_in[0];
    const float* pts = (const float*)d_in[1];
    const float* W1  = (const float*)d_in[2];
    const float* b1  = (const float*)d_in[3];
    const float* g1  = (const float*)d_in[4];
    const float* be1 = (const float*)d_in[5];
    const float* W2  = (const float*)d_in[6];
    const float* b2  = (const float*)d_in[7];
    const float* g2  = (const float*)d_in[8];
    const float* be2 = (const float*)d_in[9];
    const float* W3  = (const float*)d_in[10];
    const float* b3  = (const float*)d_in[11];
    float* out = (float*)d_out;

    cudaFuncSetAttribute(k_aux, cudaFuncAttributeMaxDynamicSharedMemorySize, 69632);
    cudaFuncSetAttribute(k_knn, cudaFuncAttributeMaxDynamicSharedMemorySize, 163840);
    cudaFuncSetAttribute(k_l1,  cudaFuncAttributeMaxDynamicSharedMemorySize, 86272);
    cudaFuncSetAttribute(k_l2,  cudaFuncAttributeMaxDynamicSharedMemorySize, 82944);
    cudaFuncSetAttribute(k_l3,  cudaFuncAttributeMaxDynamicSharedMemorySize, 98816);

    k_fps<<<NB*CLU, FPS_T>>>(xyz);
    k_aux<<<320, 1024, 69632>>>(xyz, pts);
    k_knn<<<128, 256, 163840>>>(out);
    k_l1 <<<1024, 128, 86272>>>(W1, b1);
    k_fin<<<1, 64>>>(g1, be1, 0);
    k_l2 <<<1024, 128, 82944>>>(W2, b2);
    k_fin<<<1, 64>>>(g2, be2, 1);
    k_l3 <<<1024, 128, 98816>>>(W3, b3, out);
}